// round 10
// baseline (speedup 1.0000x reference)
#include <cuda_runtime.h>
#include <cstdint>
#include <cstddef>

typedef unsigned long long u64;

// ---------------------------------------------------------------------------
// Shapes: B=4, SQ=2048, SK=1024, D=1024. All GEMM K = 1024.
// ---------------------------------------------------------------------------

// scratch (device globals; allocation forbidden)
__device__ __align__(256) float g_k  [4ull * 1024 * 1024];   // k  [b*1024+s][d]
__device__ __align__(256) float g_vt [1024ull * 4096];       // vT [d][b*1024+s]
__device__ __align__(256) float g_qy [8192ull * 1024];       // qy
__device__ __align__(256) float g_inv[8192ull * 1024];       // inv
__device__ __align__(256) float g_qk [8192ull * 1024];       // qk / attn

__device__ __forceinline__ u64 pack_dup(float a) {
    u64 r;
    asm("mov.b64 %0, {%1, %1};" : "=l"(r) : "f"(a));
    return r;
}
__device__ __forceinline__ void fma2(u64 &d, u64 a, u64 b) {
    asm("fma.rn.f32x2 %0, %1, %2, %0;" : "+l"(d) : "l"(a), "l"(b));
}

#define RSA 132                  // A smem row stride (floats)
#define RSB 264                  // B smem row stride (floats; 128 dup u64 + pad)
#define ABUF (8 * RSA)           // one A slab
#define BBUF (8 * RSB)           // one B slab

// ---------------------------------------------------------------------------
// Core: C[m0+128, n0+128] = sum_k A[m,k] * B[n,k]  (NT), fp32, K=1024.
// 256 threads; thread (tx=tid&15, ty=tid>>4) owns rows m0+8ty..+7 and
// cols n0+8tx..+7. acc[i][j] = f32x2 (rows 2i,2i+1; col j) via FFMA2.
// A smem [k][m] natural (row-pairs feed FFMA2 'a' directly, NO dup).
// B smem [k][grouped dup]: col n stored as dup-u64 at group p=(n&6)>>1,
//   entry q=2*(n>>3)+(n&1)  ->  per-kk reads are 256B-contiguous per LDS.128.
// K-slab 8, 2-stage LDG prefetch, one barrier per slab.
// epi: 0 = +bias[n] | 1 = +bias[m] | 2 = /= aux[r*ldC+col] | 3 = none
// ---------------------------------------------------------------------------
__device__ __forceinline__ void run_gemm(
    const float* __restrict__ A, int ldA,
    const float* __restrict__ B, int ldB,
    float* __restrict__ C, int ldC,
    const float* __restrict__ aux, int epi,
    int m0, int n0, float* sA, float* sB)
{
    const int tid = threadIdx.x;
    const int tx  = tid & 15, ty = tid >> 4;
    const int row = tid >> 1, ks = (tid & 1) * 4;

    const float* Ag = A + (size_t)(m0 + row) * ldA + ks;
    const float* Bg = B + (size_t)(n0 + row) * ldB + ks;

    // B dup slot for this thread's column (float offset within a kk row)
    const int bslot = 64 * ((row & 6) >> 1) + 4 * (row >> 3) + 2 * (row & 1);

    u64 acc[4][8];
    #pragma unroll
    for (int i = 0; i < 4; i++)
        #pragma unroll
        for (int j = 0; j < 8; j++) acc[i][j] = 0ull;

    float4 ra = *(const float4*)Ag;
    float4 rb = *(const float4*)Bg;

    for (int s = 0; s < 128; s++) {
        const int buf = s & 1;

        // ---- store staged slab ----
        {
            float* ab = sA + buf * ABUF + ks * RSA + row;
            ab[0 * RSA] = ra.x;
            ab[1 * RSA] = ra.y;
            ab[2 * RSA] = ra.z;
            ab[3 * RSA] = ra.w;
            float* bb = sB + buf * BBUF + ks * RSB + bslot;
            *(u64*)(bb + 0 * RSB) = pack_dup(rb.x);
            *(u64*)(bb + 1 * RSB) = pack_dup(rb.y);
            *(u64*)(bb + 2 * RSB) = pack_dup(rb.z);
            *(u64*)(bb + 3 * RSB) = pack_dup(rb.w);
        }
        __syncthreads();

        // ---- prefetch next slab ----
        if (s + 1 < 128) {
            const int k0 = (s + 1) * 8;
            ra = *(const float4*)(Ag + k0);
            rb = *(const float4*)(Bg + k0);
        }

        // ---- compute 8 kk ----
        const float* ca = sA + buf * ABUF + 8 * ty;
        const float* cb = sB + buf * BBUF + 4 * tx;
        #pragma unroll
        for (int kk = 0; kk < 8; kk++) {
            // A: rows 8ty..8ty+7 as 4 natural f32x2 pairs (broadcast-friendly)
            ulonglong2 aA = *(const ulonglong2*)(ca + kk * RSA);
            ulonglong2 aB = *(const ulonglong2*)(ca + kk * RSA + 4);
            // B: 4 contiguous-group LDS.128, each = (dup b_{2p}, dup b_{2p+1})
            ulonglong2 b0 = *(const ulonglong2*)(cb + kk * RSB);
            ulonglong2 b1 = *(const ulonglong2*)(cb + kk * RSB + 64);
            ulonglong2 b2 = *(const ulonglong2*)(cb + kk * RSB + 128);
            ulonglong2 b3 = *(const ulonglong2*)(cb + kk * RSB + 192);
            u64 ap[4] = { aA.x, aA.y, aB.x, aB.y };
            u64 bd[8] = { b0.x, b0.y, b1.x, b1.y, b2.x, b2.y, b3.x, b3.y };
            #pragma unroll
            for (int i = 0; i < 4; i++)
                #pragma unroll
                for (int j = 0; j < 8; j++)
                    fma2(acc[i][j], ap[i], bd[j]);
        }
    }

    // ---- epilogue ----
    const int cb0 = n0 + 8 * tx;
    float4 bn0, bn1;
    if (epi == 0) {
        bn0 = *(const float4*)(aux + cb0);
        bn1 = *(const float4*)(aux + cb0 + 4);
    }
    #pragma unroll
    for (int i = 0; i < 4; i++) {
        const int re = m0 + 8 * ty + 2 * i;
        float ve[8], vo[8];
        #pragma unroll
        for (int j = 0; j < 8; j++) {
            float2 f = *reinterpret_cast<float2*>(&acc[i][j]);
            ve[j] = f.x;
            vo[j] = f.y;
        }
        if (epi == 0) {
            ve[0] += bn0.x; ve[1] += bn0.y; ve[2] += bn0.z; ve[3] += bn0.w;
            ve[4] += bn1.x; ve[5] += bn1.y; ve[6] += bn1.z; ve[7] += bn1.w;
            vo[0] += bn0.x; vo[1] += bn0.y; vo[2] += bn0.z; vo[3] += bn0.w;
            vo[4] += bn1.x; vo[5] += bn1.y; vo[6] += bn1.z; vo[7] += bn1.w;
        } else if (epi == 1) {
            const float be = aux[re], bo = aux[re + 1];
            #pragma unroll
            for (int j = 0; j < 8; j++) { ve[j] += be; vo[j] += bo; }
        } else if (epi == 2) {
            const float* de = aux + (size_t)re * ldC + cb0;
            const float* dp = aux + (size_t)(re + 1) * ldC + cb0;
            const float4 d0 = *(const float4*)(de);
            const float4 d1 = *(const float4*)(de + 4);
            const float4 d2 = *(const float4*)(dp);
            const float4 d3 = *(const float4*)(dp + 4);
            ve[0] /= d0.x; ve[1] /= d0.y; ve[2] /= d0.z; ve[3] /= d0.w;
            ve[4] /= d1.x; ve[5] /= d1.y; ve[6] /= d1.z; ve[7] /= d1.w;
            vo[0] /= d2.x; vo[1] /= d2.y; vo[2] /= d2.z; vo[3] /= d2.w;
            vo[4] /= d3.x; vo[5] /= d3.y; vo[6] /= d3.z; vo[7] /= d3.w;
        }
        float* ce = C + (size_t)re * ldC + cb0;
        float* co = C + (size_t)(re + 1) * ldC + cb0;
        *(float4*)(ce)     = *(float4*)&ve[0];
        *(float4*)(ce + 4) = *(float4*)&ve[4];
        *(float4*)(co)     = *(float4*)&vo[0];
        *(float4*)(co + 4) = *(float4*)&vo[4];
    }
}

// ---------------------------------------------------------------------------
// Fused kernel: the 4 independent linears in one grid (1536 CTAs).
//   [0,256)     k   = y @ W2^T + b2      M=4096, N=1024: 32 x 8 tiles
//   [256,512)   vT  = W3 @ y^T + b3[m]   M=1024, N=4096: 8 x 32, ldC=4096
//   [512,1024)  qy  = x @ W4^T + b4      M=8192, N=1024: 64 x 8
//   [1024,1536) inv = x @ W5^T + b5      M=8192, N=1024: 64 x 8
// ---------------------------------------------------------------------------
__global__ void __launch_bounds__(256, 2) k_fused(
    const float* __restrict__ x, const float* __restrict__ y,
    const float* __restrict__ W2, const float* __restrict__ b2,
    const float* __restrict__ W3, const float* __restrict__ b3,
    const float* __restrict__ W4, const float* __restrict__ b4,
    const float* __restrict__ W5, const float* __restrict__ b5,
    float* __restrict__ gk, float* __restrict__ gvt,
    float* __restrict__ gqy, float* __restrict__ ginv)
{
    __shared__ __align__(16) float sA[2 * ABUF];
    __shared__ __align__(16) float sB[2 * BBUF];

    const int t = blockIdx.x;
    const float *A, *B, *aux;
    float* C;
    int ldC, epi, m0, n0;

    if (t < 256) {
        A = y;  B = W2; C = gk;   aux = b2; ldC = 1024; epi = 0;
        m0 = (t >> 3) << 7; n0 = (t & 7) << 7;
    } else if (t < 512) {
        const int u = t - 256;
        A = W3; B = y;  C = gvt;  aux = b3; ldC = 4096; epi = 1;
        m0 = (u >> 5) << 7; n0 = (u & 31) << 7;
    } else if (t < 1024) {
        const int u = t - 512;
        A = x;  B = W4; C = gqy;  aux = b4; ldC = 1024; epi = 0;
        m0 = (u >> 3) << 7; n0 = (u & 7) << 7;
    } else {
        const int u = t - 1024;
        A = x;  B = W5; C = ginv; aux = b5; ldC = 1024; epi = 0;
        m0 = (u >> 3) << 7; n0 = (u & 7) << 7;
    }
    run_gemm(A, 1024, B, 1024, C, ldC, aux, epi, m0, n0, sA, sB);
}

// qk = (qy @ k^T) / inv, per batch z
__global__ void __launch_bounds__(256, 2) k_qk(
    const float* __restrict__ gqy, const float* __restrict__ gk,
    const float* __restrict__ ginv, float* __restrict__ gqk)
{
    __shared__ __align__(16) float sA[2 * ABUF];
    __shared__ __align__(16) float sB[2 * BBUF];
    const size_t z = blockIdx.z;
    run_gemm(gqy + z * (2048ull * 1024), 1024,
             gk  + z * (1024ull * 1024), 1024,
             gqk + z * (2048ull * 1024), 1024,
             ginv + z * (2048ull * 1024), 2,
             blockIdx.y * 128, blockIdx.x * 128, sA, sB);
}

// out = attn @ vT^T, per batch z (B row n lives at gvt + z*1024 + n*4096)
__global__ void __launch_bounds__(256, 2) k_av(
    const float* __restrict__ gqk, const float* __restrict__ gvt,
    float* __restrict__ out)
{
    __shared__ __align__(16) float sA[2 * ABUF];
    __shared__ __align__(16) float sB[2 * BBUF];
    const size_t z = blockIdx.z;
    run_gemm(gqk + z * (2048ull * 1024), 1024,
             gvt + z * 1024, 4096,
             out + z * (2048ull * 1024), 1024,
             nullptr, 3,
             blockIdx.y * 128, blockIdx.x * 128, sA, sB);
}

// ---------------------------------------------------------------------------
// Row softmax over 1024, in place. 1 block/row, 256 threads. (validated)
// ---------------------------------------------------------------------------
__global__ void __launch_bounds__(256) softmax1024(float* __restrict__ data)
{
    float* p = data + (size_t)blockIdx.x * 1024;
    const int t = threadIdx.x, lane = t & 31, warp = t >> 5;
    __shared__ float red[8];
    __shared__ float stat[2];

    float4 x = *((const float4*)p + t);
    float m = fmaxf(fmaxf(x.x, x.y), fmaxf(x.z, x.w));
    #pragma unroll
    for (int o = 16; o > 0; o >>= 1) m = fmaxf(m, __shfl_xor_sync(~0u, m, o));
    if (lane == 0) red[warp] = m;
    __syncthreads();
    if (t == 0) {
        float mm = red[0];
        #pragma unroll
        for (int i = 1; i < 8; i++) mm = fmaxf(mm, red[i]);
        stat[0] = mm;
    }
    __syncthreads();
    const float bm = stat[0];
    x.x = __expf(x.x - bm); x.y = __expf(x.y - bm);
    x.z = __expf(x.z - bm); x.w = __expf(x.w - bm);
    float s = (x.x + x.y) + (x.z + x.w);
    #pragma unroll
    for (int o = 16; o > 0; o >>= 1) s += __shfl_xor_sync(~0u, s, o);
    __syncthreads();
    if (lane == 0) red[warp] = s;
    __syncthreads();
    if (t == 0) {
        float ss = red[0];
        #pragma unroll
        for (int i = 1; i < 8; i++) ss += red[i];
        stat[1] = 1.0f / ss;
    }
    __syncthreads();
    const float r = stat[1];
    x.x *= r; x.y *= r; x.z *= r; x.w *= r;
    *((float4*)p + t) = x;
}

// ---------------------------------------------------------------------------
static float* symaddr(const void* s) {
    void* p = nullptr;
    cudaGetSymbolAddress(&p, s);
    return (float*)p;
}

extern "C" void kernel_launch(void* const* d_in, const int* in_sizes, int n_in,
                              void* d_out, int out_size)
{
    (void)in_sizes; (void)n_in; (void)out_size;
    const float* x  = (const float*)d_in[0];
    const float* y  = (const float*)d_in[1];
    const float* W2 = (const float*)d_in[4];  const float* b2 = (const float*)d_in[5];
    const float* W3 = (const float*)d_in[6];  const float* b3 = (const float*)d_in[7];
    const float* W4 = (const float*)d_in[8];  const float* b4 = (const float*)d_in[9];
    const float* W5 = (const float*)d_in[10]; const float* b5 = (const float*)d_in[11];
    float* out = (float*)d_out;

    float* gk   = symaddr(g_k);
    float* gvt  = symaddr(g_vt);
    float* gqy  = symaddr(g_qy);
    float* ginv = symaddr(g_inv);
    float* gqk  = symaddr(g_qk);

    // 1) four independent linears, one launch (1536 tiles of 128x128)
    k_fused<<<1536, 256>>>(x, y, W2, b2, W3, b3, W4, b4, W5, b5,
                           gk, gvt, gqy, ginv);

    // 2) qk = (qy @ k^T) / inv   (8 x 16 x 4 tiles)
    k_qk<<<dim3(8, 16, 4), 256>>>(gqy, gk, ginv, gqk);

    // 3) softmax rows (in place)
    softmax1024<<<8192, 256>>>(gqk);

    // 4) out = attn @ v          (8 x 16 x 4 tiles)
    k_av<<<dim3(8, 16, 4), 256>>>(gqk, gvt, out);
}

// round 11
// speedup vs baseline: 1.4492x; 1.4492x over previous
#include <cuda_runtime.h>
#include <cstddef>

// ---------------------------------------------------------------------------
// Shapes (fixed by the problem)
//   B=4, SQ=2048, SK=1024, D=1024
// Round-1 kernel (best known: 2113us) + ONE change: B smem rows get a 4-float
// gap every 32 floats (f' = f + 4*(f>>5), stride 140) which provably reduces
// the B fragment LDS.128s from 4-way bank conflicts to the 2-wavefront floor.
// ---------------------------------------------------------------------------
#define BB   4
#define SQ   2048
#define SK   1024
#define DD   1024

// Scratch (device globals; allocation in kernel_launch is forbidden)
__device__ float g_k  [BB * SK * DD];   // 16 MB
__device__ float g_v  [BB * SK * DD];   // 16 MB
__device__ float g_qy [BB * SQ * DD];   // 32 MB
__device__ float g_inv[BB * SQ * DD];   // 32 MB
__device__ float g_qk [BB * SQ * SK];   // 32 MB

typedef unsigned long long u64;

__device__ __forceinline__ u64 pack_dup(float a) {
    u64 r;
    asm("mov.b64 %0, {%1, %1};" : "=l"(r) : "f"(a));
    return r;
}
__device__ __forceinline__ void fma2(u64 &d, u64 a, u64 b) {
    // packed f32x2 FMA (SASS FFMA2) — 2x fp32 throughput vs scalar FFMA
    asm("fma.rn.f32x2 %0, %1, %2, %0;" : "+l"(d) : "l"(a), "l"(b));
}

// B-row swizzle: insert a 4-float gap after every 32 floats.
__device__ __forceinline__ int bswz(int f) { return f + 4 * (f >> 5); }
#define RSB 140   // 128 data + 3 gaps(12) = 140 floats per B row

// ---------------------------------------------------------------------------
// Tiled GEMM: C[M,N] = A[M,K] * op(B)  (+ epilogue)
//   MODEB = 0 : B is [N,K] row-major (NT, dot of rows)  — linears, qk
//   MODEB = 1 : B is [K,N] row-major (NN)               — attn @ v
//   EPI   = 0 : C += bias[n]            (aux = bias, len N)
//   EPI   = 1 : C /= aux[same index]    (aux shaped like C) — qk/inv_scale
//   EPI   = 2 : none
// Tiles: 128x128x16, 256 threads, 8x8 per thread via f32x2 packed FMA.
// ---------------------------------------------------------------------------
template <int MODEB, int EPI>
__global__ __launch_bounds__(256) void gemm128(
    const float* __restrict__ A, const float* __restrict__ B,
    const float* __restrict__ aux, float* __restrict__ C,
    int M, int N, int K,
    size_t sA, size_t sB, size_t sC, size_t sX)
{
    __shared__ float As[16][132];
    __shared__ float Bs[16][RSB];

    const int tid = threadIdx.x;
    const int tx = tid & 15;        // column group
    const int ty = tid >> 4;        // row group
    const int z  = blockIdx.z;

    A   += (size_t)z * sA;
    B   += (size_t)z * sB;
    C   += (size_t)z * sC;
    aux += (size_t)z * sX;

    const int rm = blockIdx.y * 128;  // row base
    const int cn = blockIdx.x * 128;  // col base

    u64 acc[8][4];
    #pragma unroll
    for (int i = 0; i < 8; i++)
        #pragma unroll
        for (int p = 0; p < 4; p++) acc[i][p] = 0ull;

    // swizzled float-offset of this thread's B fragment within a kk row
    const int boff = tx * 8 + 4 * (tx >> 2);

    for (int k0 = 0; k0 < K; k0 += 16) {
        // ---- load A tile [128 x 16], store transposed As[k][row] ----
        #pragma unroll
        for (int i = 0; i < 2; i++) {
            int f   = tid + i * 256;        // 0..511 float4 slots
            int row = f >> 2;
            int ks  = (f & 3) * 4;
            float4 v = *(const float4*)(A + (size_t)(rm + row) * K + k0 + ks);
            As[ks + 0][row] = v.x;
            As[ks + 1][row] = v.y;
            As[ks + 2][row] = v.z;
            As[ks + 3][row] = v.w;
        }
        // ---- load B tile ----
        if (MODEB == 0) {
            // B[N,K]: transposed store at swizzled column
            #pragma unroll
            for (int i = 0; i < 2; i++) {
                int f   = tid + i * 256;
                int row = f >> 2;
                int ks  = (f & 3) * 4;
                int rw  = bswz(row);
                float4 v = *(const float4*)(B + (size_t)(cn + row) * K + k0 + ks);
                Bs[ks + 0][rw] = v.x;
                Bs[ks + 1][rw] = v.y;
                Bs[ks + 2][rw] = v.z;
                Bs[ks + 3][rw] = v.w;
            }
        } else {
            // B[K,N]: direct copy, float4 at swizzled column (4-aligned
            // chunks never cross a 32-float block, so they stay contiguous)
            #pragma unroll
            for (int i = 0; i < 2; i++) {
                int f  = tid + i * 256;
                int kr = f >> 5;
                int ns = (f & 31) * 4;
                float4 v = *(const float4*)(B + (size_t)(k0 + kr) * N + cn + ns);
                *(float4*)&Bs[kr][bswz(ns)] = v;
            }
        }
        __syncthreads();

        #pragma unroll
        for (int kk = 0; kk < 16; kk++) {
            float a[8];
            *(float4*)&a[0] = *(const float4*)&As[kk][ty * 8];
            *(float4*)&a[4] = *(const float4*)&As[kk][ty * 8 + 4];
            u64 bv[4];
            const u64* b64 = (const u64*)&Bs[kk][boff];
            bv[0] = b64[0]; bv[1] = b64[1]; bv[2] = b64[2]; bv[3] = b64[3];
            #pragma unroll
            for (int i = 0; i < 8; i++) {
                u64 ad = pack_dup(a[i]);
                #pragma unroll
                for (int p = 0; p < 4; p++) fma2(acc[i][p], ad, bv[p]);
            }
        }
        __syncthreads();
    }

    // ---- epilogue + store ----
    #pragma unroll
    for (int i = 0; i < 8; i++) {
        int r = rm + ty * 8 + i;
        size_t base = (size_t)r * N + cn + tx * 8;
        float c[8];
        #pragma unroll
        for (int p = 0; p < 4; p++) {
            float2 f2 = *(float2*)&acc[i][p];
            c[2 * p + 0] = f2.x;
            c[2 * p + 1] = f2.y;
        }
        if (EPI == 0) {
            #pragma unroll
            for (int j = 0; j < 8; j++) c[j] += aux[cn + tx * 8 + j];
        } else if (EPI == 1) {
            #pragma unroll
            for (int j = 0; j < 8; j++) c[j] /= aux[base + j];
        }
        *(float4*)(C + base)     = *(float4*)&c[0];
        *(float4*)(C + base + 4) = *(float4*)&c[4];
    }
}

// ---------------------------------------------------------------------------
// Row softmax over N=1024, one 256-thread block per row, in place.
// ---------------------------------------------------------------------------
__global__ __launch_bounds__(256) void softmax1024(float* __restrict__ data)
{
    float* p = data + (size_t)blockIdx.x * 1024;
    const int t    = threadIdx.x;
    const int lane = t & 31;
    const int warp = t >> 5;

    __shared__ float redbuf[8];
    __shared__ float stat[2];

    float4 x = *((const float4*)p + t);

    // --- max ---
    float m = fmaxf(fmaxf(x.x, x.y), fmaxf(x.z, x.w));
    #pragma unroll
    for (int o = 16; o > 0; o >>= 1)
        m = fmaxf(m, __shfl_xor_sync(0xffffffffu, m, o));
    if (lane == 0) redbuf[warp] = m;
    __syncthreads();
    if (t == 0) {
        float mm = redbuf[0];
        #pragma unroll
        for (int i = 1; i < 8; i++) mm = fmaxf(mm, redbuf[i]);
        stat[0] = mm;
    }
    __syncthreads();
    const float bm = stat[0];

    // --- exp ---
    x.x = __expf(x.x - bm);
    x.y = __expf(x.y - bm);
    x.z = __expf(x.z - bm);
    x.w = __expf(x.w - bm);

    // --- sum ---
    float s = (x.x + x.y) + (x.z + x.w);
    #pragma unroll
    for (int o = 16; o > 0; o >>= 1)
        s += __shfl_xor_sync(0xffffffffu, s, o);
    __syncthreads();           // protect redbuf reuse
    if (lane == 0) redbuf[warp] = s;
    __syncthreads();
    if (t == 0) {
        float ss = redbuf[0];
        #pragma unroll
        for (int i = 1; i < 8; i++) ss += redbuf[i];
        stat[1] = 1.0f / ss;
    }
    __syncthreads();
    const float r = stat[1];

    x.x *= r; x.y *= r; x.z *= r; x.w *= r;
    *((float4*)p + t) = x;
}

// ---------------------------------------------------------------------------
// kernel_launch
// inputs: 0:x 1:y 2:W1 3:b1 4:W2 5:b2 6:W3 7:b3 8:W4 9:b4 10:W5 11:b5
// ---------------------------------------------------------------------------
extern "C" void kernel_launch(void* const* d_in, const int* in_sizes, int n_in,
                              void* d_out, int out_size)
{
    (void)in_sizes; (void)n_in; (void)out_size;

    const float* x  = (const float*)d_in[0];
    const float* y  = (const float*)d_in[1];
    const float* W2 = (const float*)d_in[4];
    const float* b2 = (const float*)d_in[5];
    const float* W3 = (const float*)d_in[6];
    const float* b3 = (const float*)d_in[7];
    const float* W4 = (const float*)d_in[8];
    const float* b4 = (const float*)d_in[9];
    const float* W5 = (const float*)d_in[10];
    const float* b5 = (const float*)d_in[11];
    float* out = (float*)d_out;

    void *pk, *pv, *pqy, *pinv, *pqk;
    cudaGetSymbolAddress(&pk,   g_k);
    cudaGetSymbolAddress(&pv,   g_v);
    cudaGetSymbolAddress(&pqy,  g_qy);
    cudaGetSymbolAddress(&pinv, g_inv);
    cudaGetSymbolAddress(&pqk,  g_qk);
    float* gk   = (float*)pk;
    float* gv   = (float*)pv;
    float* gqy  = (float*)pqy;
    float* ginv = (float*)pinv;
    float* gqk  = (float*)pqk;

    const dim3 blk(256);

    // linears (batch flattened into M)
    {
        dim3 grid_y(DD / 128, (BB * SK) / 128, 1);   // (8, 32)
        gemm128<0, 0><<<grid_y, blk>>>(y, W2, b2, gk, BB * SK, DD, DD, 0, 0, 0, 0);
        gemm128<0, 0><<<grid_y, blk>>>(y, W3, b3, gv, BB * SK, DD, DD, 0, 0, 0, 0);
        dim3 grid_x(DD / 128, (BB * SQ) / 128, 1);   // (8, 64)
        gemm128<0, 0><<<grid_x, blk>>>(x, W4, b4, gqy,  BB * SQ, DD, DD, 0, 0, 0, 0);
        gemm128<0, 0><<<grid_x, blk>>>(x, W5, b5, ginv, BB * SQ, DD, DD, 0, 0, 0, 0);
    }

    // qk = (qy @ k^T) / inv, per batch
    {
        dim3 grid(SK / 128, SQ / 128, BB);           // (8, 16, 4)
        gemm128<0, 1><<<grid, blk>>>(gqy, gk, ginv, gqk,
                                     SQ, SK, DD,
                                     (size_t)SQ * DD, (size_t)SK * DD,
                                     (size_t)SQ * SK, (size_t)SQ * DD);
    }

    // softmax rows (B*SQ rows of SK=1024)
    softmax1024<<<BB * SQ, blk>>>(gqk);

    // out = attn @ v, per batch
    {
        dim3 grid(DD / 128, SQ / 128, BB);           // (8, 16, 4)
        gemm128<1, 2><<<grid, blk>>>(gqk, gv, nullptr, out,
                                     SQ, DD, SK,
                                     (size_t)SQ * SK, (size_t)SK * DD,
                                     (size_t)SQ * DD, 0);
    }
}

// round 12
// speedup vs baseline: 1.5005x; 1.0354x over previous
#include <cuda_runtime.h>
#include <cstddef>

// ---------------------------------------------------------------------------
// Shapes (fixed): B=4, SQ=2048, SK=1024, D=1024
// R11 kernel (best: 1860us) + ONE change: k-slab 16->8, double-buffered smem,
// register prefetch of the next slab, ONE barrier per slab (proof: sync(s+1)
// orders compute(buf) before the s+2 overwrite of buf). Inner loop identical.
// ---------------------------------------------------------------------------
#define BB   4
#define SQ   2048
#define SK   1024
#define DD   1024

__device__ float g_k  [BB * SK * DD];
__device__ float g_v  [BB * SK * DD];
__device__ float g_qy [BB * SQ * DD];
__device__ float g_inv[BB * SQ * DD];
__device__ float g_qk [BB * SQ * SK];

typedef unsigned long long u64;

__device__ __forceinline__ u64 pack_dup(float a) {
    u64 r;
    asm("mov.b64 %0, {%1, %1};" : "=l"(r) : "f"(a));
    return r;
}
__device__ __forceinline__ void fma2(u64 &d, u64 a, u64 b) {
    asm("fma.rn.f32x2 %0, %1, %2, %0;" : "+l"(d) : "l"(a), "l"(b));
}

// B-row swizzle: insert a 4-float gap after every 32 floats (validated R11).
__device__ __forceinline__ int bswz(int f) { return f + 4 * (f >> 5); }
#define RSB 140

// ---------------------------------------------------------------------------
// Tiled GEMM: C[M,N] = A[M,K] * op(B)  (+ epilogue)
//   MODEB = 0 : B is [N,K] row-major (NT) — linears, qk
//   MODEB = 1 : B is [K,N] row-major (NN) — attn @ v
//   EPI: 0 = +bias[n] | 1 = /= aux | 2 = none
// Tiles: 128x128, k-slab 8, 256 threads, 8x8/thread via FFMA2.
// ---------------------------------------------------------------------------
template <int MODEB, int EPI>
__global__ __launch_bounds__(256, 2) void gemm128(
    const float* __restrict__ A, const float* __restrict__ B,
    const float* __restrict__ aux, float* __restrict__ C,
    int M, int N, int K,
    size_t sA, size_t sB, size_t sC, size_t sX)
{
    __shared__ float As[2][8][132];
    __shared__ float Bs[2][8][RSB];

    const int tid = threadIdx.x;
    const int tx = tid & 15;
    const int ty = tid >> 4;
    const int z  = blockIdx.z;

    A   += (size_t)z * sA;
    B   += (size_t)z * sB;
    C   += (size_t)z * sC;
    aux += (size_t)z * sX;

    const int rm = blockIdx.y * 128;
    const int cn = blockIdx.x * 128;

    // per-thread load coordinates (one float4 each for A and B per slab)
    const int lrow = tid >> 1;            // 0..127
    const int lks  = (tid & 1) * 4;       // 0 or 4
    const int brow = bswz(lrow);          // swizzled B column (MODEB==0)
    const int bkr  = tid >> 5;            // 0..7   (MODEB==1)
    const int bns  = (tid & 31) * 4;      // 0..124 (MODEB==1)
    const int bnsw = bswz(bns);

    const float* Ag = A + (size_t)(rm + lrow) * K + lks;
    const float* Bg = (MODEB == 0)
        ? B + (size_t)(cn + lrow) * K + lks
        : B + (size_t)bkr * N + cn + bns;

    u64 acc[8][4];
    #pragma unroll
    for (int i = 0; i < 8; i++)
        #pragma unroll
        for (int p = 0; p < 4; p++) acc[i][p] = 0ull;

    const int boff = tx * 8 + 4 * (tx >> 2);   // swizzled B fragment offset
    const int nsl = K >> 3;

    float4 ra = *(const float4*)Ag;
    float4 rb = *(const float4*)Bg;

    for (int s = 0; s < nsl; s++) {
        const int buf = s & 1;

        // ---- store staged slab ----
        {
            float* ap = &As[buf][lks][lrow];
            ap[0 * 132] = ra.x;
            ap[1 * 132] = ra.y;
            ap[2 * 132] = ra.z;
            ap[3 * 132] = ra.w;
            if (MODEB == 0) {
                float* bp = &Bs[buf][lks][brow];
                bp[0 * RSB] = rb.x;
                bp[1 * RSB] = rb.y;
                bp[2 * RSB] = rb.z;
                bp[3 * RSB] = rb.w;
            } else {
                *(float4*)&Bs[buf][bkr][bnsw] = rb;
            }
        }
        __syncthreads();

        // ---- prefetch next slab (drains under compute) ----
        if (s + 1 < nsl) {
            const int k1 = (s + 1) * 8;
            ra = *(const float4*)(Ag + k1);
            rb = (MODEB == 0) ? *(const float4*)(Bg + k1)
                              : *(const float4*)(Bg + (size_t)k1 * N);
        }

        // ---- compute 8 kk (identical to R11 inner loop) ----
        #pragma unroll
        for (int kk = 0; kk < 8; kk++) {
            float a[8];
            *(float4*)&a[0] = *(const float4*)&As[buf][kk][ty * 8];
            *(float4*)&a[4] = *(const float4*)&As[buf][kk][ty * 8 + 4];
            u64 bv[4];
            const u64* b64 = (const u64*)&Bs[buf][kk][boff];
            bv[0] = b64[0]; bv[1] = b64[1]; bv[2] = b64[2]; bv[3] = b64[3];
            #pragma unroll
            for (int i = 0; i < 8; i++) {
                u64 ad = pack_dup(a[i]);
                #pragma unroll
                for (int p = 0; p < 4; p++) fma2(acc[i][p], ad, bv[p]);
            }
        }
    }

    // ---- epilogue + store (unchanged) ----
    #pragma unroll
    for (int i = 0; i < 8; i++) {
        int r = rm + ty * 8 + i;
        size_t base = (size_t)r * N + cn + tx * 8;
        float c[8];
        #pragma unroll
        for (int p = 0; p < 4; p++) {
            float2 f2 = *(float2*)&acc[i][p];
            c[2 * p + 0] = f2.x;
            c[2 * p + 1] = f2.y;
        }
        if (EPI == 0) {
            #pragma unroll
            for (int j = 0; j < 8; j++) c[j] += aux[cn + tx * 8 + j];
        } else if (EPI == 1) {
            #pragma unroll
            for (int j = 0; j < 8; j++) c[j] /= aux[base + j];
        }
        *(float4*)(C + base)     = *(float4*)&c[0];
        *(float4*)(C + base + 4) = *(float4*)&c[4];
    }
}

// ---------------------------------------------------------------------------
// Row softmax over N=1024, one 256-thread block per row, in place.
// ---------------------------------------------------------------------------
__global__ __launch_bounds__(256) void softmax1024(float* __restrict__ data)
{
    float* p = data + (size_t)blockIdx.x * 1024;
    const int t    = threadIdx.x;
    const int lane = t & 31;
    const int warp = t >> 5;

    __shared__ float redbuf[8];
    __shared__ float stat[2];

    float4 x = *((const float4*)p + t);

    float m = fmaxf(fmaxf(x.x, x.y), fmaxf(x.z, x.w));
    #pragma unroll
    for (int o = 16; o > 0; o >>= 1)
        m = fmaxf(m, __shfl_xor_sync(0xffffffffu, m, o));
    if (lane == 0) redbuf[warp] = m;
    __syncthreads();
    if (t == 0) {
        float mm = redbuf[0];
        #pragma unroll
        for (int i = 1; i < 8; i++) mm = fmaxf(mm, redbuf[i]);
        stat[0] = mm;
    }
    __syncthreads();
    const float bm = stat[0];

    x.x = __expf(x.x - bm);
    x.y = __expf(x.y - bm);
    x.z = __expf(x.z - bm);
    x.w = __expf(x.w - bm);

    float s = (x.x + x.y) + (x.z + x.w);
    #pragma unroll
    for (int o = 16; o > 0; o >>= 1)
        s += __shfl_xor_sync(0xffffffffu, s, o);
    __syncthreads();
    if (lane == 0) redbuf[warp] = s;
    __syncthreads();
    if (t == 0) {
        float ss = redbuf[0];
        #pragma unroll
        for (int i = 1; i < 8; i++) ss += redbuf[i];
        stat[1] = 1.0f / ss;
    }
    __syncthreads();
    const float r = stat[1];

    x.x *= r; x.y *= r; x.z *= r; x.w *= r;
    *((float4*)p + t) = x;
}

// ---------------------------------------------------------------------------
// kernel_launch
// inputs: 0:x 1:y 2:W1 3:b1 4:W2 5:b2 6:W3 7:b3 8:W4 9:b4 10:W5 11:b5
// ---------------------------------------------------------------------------
extern "C" void kernel_launch(void* const* d_in, const int* in_sizes, int n_in,
                              void* d_out, int out_size)
{
    (void)in_sizes; (void)n_in; (void)out_size;

    const float* x  = (const float*)d_in[0];
    const float* y  = (const float*)d_in[1];
    const float* W2 = (const float*)d_in[4];
    const float* b2 = (const float*)d_in[5];
    const float* W3 = (const float*)d_in[6];
    const float* b3 = (const float*)d_in[7];
    const float* W4 = (const float*)d_in[8];
    const float* b4 = (const float*)d_in[9];
    const float* W5 = (const float*)d_in[10];
    const float* b5 = (const float*)d_in[11];
    float* out = (float*)d_out;

    void *pk, *pv, *pqy, *pinv, *pqk;
    cudaGetSymbolAddress(&pk,   g_k);
    cudaGetSymbolAddress(&pv,   g_v);
    cudaGetSymbolAddress(&pqy,  g_qy);
    cudaGetSymbolAddress(&pinv, g_inv);
    cudaGetSymbolAddress(&pqk,  g_qk);
    float* gk   = (float*)pk;
    float* gv   = (float*)pv;
    float* gqy  = (float*)pqy;
    float* ginv = (float*)pinv;
    float* gqk  = (float*)pqk;

    const dim3 blk(256);

    // linears (batch flattened into M)
    {
        dim3 grid_y(DD / 128, (BB * SK) / 128, 1);   // (8, 32)
        gemm128<0, 0><<<grid_y, blk>>>(y, W2, b2, gk, BB * SK, DD, DD, 0, 0, 0, 0);
        gemm128<0, 0><<<grid_y, blk>>>(y, W3, b3, gv, BB * SK, DD, DD, 0, 0, 0, 0);
        dim3 grid_x(DD / 128, (BB * SQ) / 128, 1);   // (8, 64)
        gemm128<0, 0><<<grid_x, blk>>>(x, W4, b4, gqy,  BB * SQ, DD, DD, 0, 0, 0, 0);
        gemm128<0, 0><<<grid_x, blk>>>(x, W5, b5, ginv, BB * SQ, DD, DD, 0, 0, 0, 0);
    }

    // qk = (qy @ k^T) / inv, per batch
    {
        dim3 grid(SK / 128, SQ / 128, BB);           // (8, 16, 4)
        gemm128<0, 1><<<grid, blk>>>(gqy, gk, ginv, gqk,
                                     SQ, SK, DD,
                                     (size_t)SQ * DD, (size_t)SK * DD,
                                     (size_t)SQ * SK, (size_t)SQ * DD);
    }

    // softmax rows (B*SQ rows of SK=1024)
    softmax1024<<<BB * SQ, blk>>>(gqk);

    // out = attn @ v, per batch
    {
        dim3 grid(DD / 128, SQ / 128, BB);           // (8, 16, 4)
        gemm128<1, 2><<<grid, blk>>>(gqk, gv, nullptr, out,
                                     SQ, DD, SK,
                                     (size_t)SQ * SK, (size_t)SK * DD,
                                     (size_t)SQ * DD, 0);
    }
}